// round 16
// baseline (speedup 1.0000x reference)
#include <cuda_runtime.h>
#include <cuda_fp16.h>
#include <math.h>
#include <stdint.h>

#define Bsz 256
#define Hd  512
#define Ld  2
#define Td  64
#define Od  7
#define G4  2048
#define Kd  1024
#define BH  (Bsz*Hd)

#define LOSCALE 2048.0f
#define LOINV   (1.0f/2048.0f)

// ---- device scratch ----
__device__ __align__(16) __half g_Whi[Ld*G4*Kd];
__device__ float  g_bias[Ld*G4];
__device__ __align__(16) float  g_h[Ld*BH];
__device__ __align__(16) float  g_c[Ld*BH];
__device__ __align__(16) __half g_bhi[Ld*2*BH];   // [layer][parity][B][H]
__device__ __align__(16) __half g_blo[Ld*2*BH];
__device__ __align__(16) __half g_xhi[BH];
__device__ __align__(16) __half g_xlo[BH];
__device__ unsigned g_barcnt;

__device__ __forceinline__ unsigned smaddr(const void* p) {
    return (unsigned)__cvta_generic_to_shared(p);
}
__device__ __forceinline__ void cp16(unsigned s, const void* g) {
    asm volatile("cp.async.cg.shared.global [%0], [%1], 16;\n" :: "r"(s), "l"(g));
}
__device__ __forceinline__ void ldsm4(unsigned* r, unsigned addr) {
    asm volatile("ldmatrix.sync.aligned.m8n8.x4.shared.b16 {%0,%1,%2,%3}, [%4];\n"
        : "=r"(r[0]), "=r"(r[1]), "=r"(r[2]), "=r"(r[3]) : "r"(addr));
}
__device__ __forceinline__ void mma16816(float* c, const unsigned* a, const unsigned* b) {
    asm volatile("mma.sync.aligned.m16n8k16.row.col.f32.f16.f16.f32 "
        "{%0,%1,%2,%3}, {%4,%5,%6,%7}, {%8,%9}, {%0,%1,%2,%3};\n"
        : "+f"(c[0]), "+f"(c[1]), "+f"(c[2]), "+f"(c[3])
        : "r"(a[0]), "r"(a[1]), "r"(a[2]), "r"(a[3]), "r"(b[0]), "r"(b[1]));
}
__device__ __forceinline__ float sigf(float x) { return 1.0f / (1.0f + expf(-x)); }

// warp-parallel decode: one row per warp, 7 outputs, shfl reduction
__device__ __forceinline__ void decode_row(const float* __restrict__ Wfc,
                                           const float* __restrict__ bfc,
                                           float* __restrict__ out,
                                           int R, int t, int lane) {
    const float4* h4 = (const float4*)(g_h + BH + (size_t)R*Hd);
    float4 hr[4];
    #pragma unroll
    for (int j = 0; j < 4; j++) hr[j] = h4[lane*4 + j];
    #pragma unroll
    for (int o = 0; o < Od; o++) {
        const float4* w4 = (const float4*)(Wfc + (size_t)o*Hd);
        float acc = 0.f;
        #pragma unroll
        for (int j = 0; j < 4; j++) {
            float4 w = w4[lane*4 + j];
            acc += hr[j].x*w.x + hr[j].y*w.y + hr[j].z*w.z + hr[j].w*w.w;
        }
        #pragma unroll
        for (int s = 16; s > 0; s >>= 1) acc += __shfl_down_sync(0xFFFFFFFFu, acc, s);
        if (lane == 0) out[(size_t)R*(Td*Od) + t*Od + o] = acc + bfc[o];
    }
}

// ---- prep ----
__global__ void prep_weights(const float* __restrict__ Wih, const float* __restrict__ Whh,
                             const float* __restrict__ bih, const float* __restrict__ bhh) {
    int idx = blockIdx.x * 256 + threadIdx.x;
    if (idx >= Ld*G4*Kd) return;
    int k = idx & (Kd - 1);
    int n = (idx >> 10) & (G4 - 1);
    int l = idx >> 21;
    int u = n >> 2, gi = n & 3;
    int srow = gi * Hd + u;
    float w = (k < Hd) ? Wih[((size_t)l*G4 + srow)*Hd + k]
                       : Whh[((size_t)l*G4 + srow)*Hd + (k - Hd)];
    g_Whi[idx] = __float2half_rn(w);
    if (k == 0) g_bias[l*G4 + n] = bih[l*G4 + srow] + bhh[l*G4 + srow];
}

__global__ void prep_state(const float* __restrict__ x, const float* __restrict__ h0,
                           const float* __restrict__ c0) {
    int idx = blockIdx.x * 256 + threadIdx.x;
    if (idx == 0) g_barcnt = 0u;
    if (idx >= Ld*BH) return;
    float h = h0[idx];
    g_h[idx] = h;
    g_c[idx] = c0[idx];
    int l = idx / BH, ru = idx - l*BH;
    __half hi = __float2half_rn(h);
    int bi = (l*2 + 1)*BH + ru;           // parity 1 = "previous" for t=0
    g_bhi[bi] = hi;
    g_blo[bi] = __float2half_rn((h - __half2float(hi)) * LOSCALE);
    if (idx < BH) {
        float xv = x[idx];
        __half xh = __float2half_rn(xv);
        g_xhi[idx] = xh;
        g_xlo[idx] = __float2half_rn((xv - __half2float(xh)) * LOSCALE);
    }
}

// ---- persistent fused LSTM: split-phase, register epilogue ----
#define STRD  72                 // halves per smem row
#define ARRH  (64*STRD)          // halves per operand array
#define STGH  (3*ARRH)           // halves per stage [Ahi, Alo, Whi]
#define STGB  (STGH*2)           // 27648 bytes
#define NSTG  8
#define DSMEM (NSTG*STGB)        // 221184 bytes

__global__ __launch_bounds__(256, 1)
void lstm_persist(const float* __restrict__ Wfc, const float* __restrict__ bfc,
                  float* __restrict__ out)
{
    const int bx = blockIdx.x;
    const int tid = threadIdx.x;

    const int mTile = bx & 3, nTile = bx >> 2;
    const int bm0 = mTile * 64, bn0 = nTile * 64;
    const int Ubase = bn0 >> 2;

    extern __shared__ __align__(16) __half dynsm[];
    __shared__ float sBias2[Ld][64];
    if (tid < 128) sBias2[tid >> 6][tid & 63] = g_bias[(tid >> 6)*G4 + bn0 + (tid & 63)];

    const __half* wH[2] = { g_Whi + (size_t)bn0 * Kd, g_Whi + ((size_t)G4 + bn0) * Kd };

    const int lane = tid & 31, warp = tid >> 5;
    const int wm = warp & 3, wn = warp >> 2;       // 4 x 2 warps, 16x32 each
    const int m0w = wm*16, n0w = wn*32;
    const int gid = lane >> 2, tid4 = lane & 3;

    const unsigned smB = smaddr(dynsm);
    const unsigned aBase = smB + 2u*((unsigned)(m0w + (lane & 15))*STRD + ((lane >> 4) << 3));
    const int g2 = lane >> 3;
    const unsigned bBase = smB + 2u*((unsigned)(2*ARRH) +
                           (unsigned)(n0w + (g2 >> 1)*8 + (lane & 7))*STRD + (unsigned)((g2 & 1) << 3));

    const __half *inpHi, *inpLo, *ownHi, *ownLo, *wHiBase;
    auto setPtrs = [&](int ph) {
        int t = ph >> 1, l = ph & 1;
        int p = t & 1, pp = p ^ 1;
        wHiBase = wH[l];
        if (l == 0) {
            if (t == 0) { inpHi = g_xhi; inpLo = g_xlo; }
            else { inpHi = g_bhi + (2 + pp)*BH; inpLo = g_blo + (2 + pp)*BH; }
            ownHi = g_bhi + pp*BH;            ownLo = g_blo + pp*BH;
        } else {
            inpHi = g_bhi + p*BH;             inpLo = g_blo + p*BH;
            ownHi = g_bhi + (2 + pp)*BH;      ownLo = g_blo + (2 + pp)*BH;
        }
    };

    // chunk order: c<8 -> own half (k = 512 + 64c), c>=8 -> inp half (k = 64(c-8))
    auto load_chunk = [&](int c) {       // no commit; caller groups pairs
        const __half *ah, *al; int kcol, kw;
        if (c < 8) { ah = ownHi; al = ownLo; kcol = 64*c;       kw = 512 + 64*c; }
        else       { ah = inpHi; al = inpLo; kcol = 64*(c - 8); kw = 64*(c - 8); }
        __half* st = dynsm + (c & 7) * STGH;
        #pragma unroll
        for (int j = 0; j < 6; j++) {
            int q = tid + 256*j;
            int arr = q >> 9, qq = q & 511;
            int row = qq >> 3, qc = qq & 7;
            unsigned so = (unsigned)(arr*ARRH + row*STRD + qc*8);
            const __half* src;
            if (arr == 0)      src = ah + (size_t)(bm0 + row)*Hd + kcol + qc*8;
            else if (arr == 1) src = al + (size_t)(bm0 + row)*Hd + kcol + qc*8;
            else               src = wHiBase + (size_t)row*Kd + kw + qc*8;
            cp16(smaddr(st + so), src);
        }
    };
    auto load_pair = [&](int c) {
        load_chunk(c); load_chunk(c + 1);
        asm volatile("cp.async.commit_group;\n");
    };

    auto gemm_chunk = [&](unsigned so, float (*accH)[4], float (*accL)[4]) {
        #pragma unroll
        for (int kk = 0; kk < 64; kk += 16) {
            unsigned aH[4], aL[4], bH[2][4];
            unsigned ad = aBase + so + 2u*(unsigned)kk;
            ldsm4(aH, ad);
            ldsm4(aL, ad + 2u*ARRH);
            unsigned bd = bBase + so + 2u*(unsigned)kk;
            ldsm4(bH[0], bd);
            ldsm4(bH[1], bd + 2u*(unsigned)(16*STRD));
            #pragma unroll
            for (int ni = 0; ni < 4; ni++)
                mma16816(accH[ni], aH, &bH[ni >> 1][(ni & 1)*2]);
            #pragma unroll
            for (int ni = 0; ni < 4; ni++)
                mma16816(accL[ni], aL, &bH[ni >> 1][(ni & 1)*2]);
        }
    };

    // prologue: own-half of phase 0 (depends only on prep kernels)
    setPtrs(0);
    #pragma unroll 1
    for (int c = 0; c < 8; c += 2) load_pair(c);

    volatile unsigned* bc = &g_barcnt;
    const bool evenp = (tid4 & 1) == 0;

    for (int ph = 0; ph < 128; ph++) {
        const int t = ph >> 1, l = ph & 1;
        const int p = t & 1;

        float accH[4][4] = {};
        float accL[4][4] = {};

        // ---- own half: all 8 chunks resident, no per-chunk barriers ----
        asm volatile("cp.async.wait_group 0;\n");
        __syncthreads();
        #pragma unroll 2
        for (int c = 0; c < 8; c++)
            gemm_chunk((unsigned)(c * STGB), accH, accL);

        // ---- global barrier: all CTAs finished phase ph-1 ----
        if (tid == 0) {
            unsigned tgt = 128u * (unsigned)ph;
            while (*bc < tgt) __nanosleep(40);
        }
        __syncthreads();     // also orders own-stage reads before inp overwrites

        // ---- inp half: 4 groups of 2 chunks ----
        #pragma unroll 1
        for (int c = 8; c < 16; c += 2) load_pair(c);

        #pragma unroll 1
        for (int gpr = 0; gpr < 4; gpr++) {
            switch (3 - gpr) {
                case 3: asm volatile("cp.async.wait_group 3;\n"); break;
                case 2: asm volatile("cp.async.wait_group 2;\n"); break;
                case 1: asm volatile("cp.async.wait_group 1;\n"); break;
                default: asm volatile("cp.async.wait_group 0;\n"); break;
            }
            __syncthreads();
            gemm_chunk((unsigned)(((8 + 2*gpr) & 7) * STGB), accH, accL);
            gemm_chunk((unsigned)(((9 + 2*gpr) & 7) * STGB), accH, accL);
        }

        // ---- prefetch next phase's own half NOW (data from ph-1, complete) ----
        __syncthreads();                 // all inp-stage reads done before overwrite
        if (ph + 1 < 128) {
            setPtrs(ph + 1);
            #pragma unroll 1
            for (int c = 0; c < 8; c += 2) load_pair(c);
        }

        // ---- register epilogue: shfl-pair full gate sets, no smem tile ----
        {
            const float* sB = sBias2[l];
            #pragma unroll
            for (int ni = 0; ni < 4; ni++) {
                float v0 = accH[ni][0] + accL[ni][0]*LOINV;   // (r0, c0)
                float v1 = accH[ni][1] + accL[ni][1]*LOINV;   // (r0, c0+1)
                float v2 = accH[ni][2] + accL[ni][2]*LOINV;   // (r0+8, c0)
                float v3 = accH[ni][3] + accL[ni][3]*LOINV;   // (r0+8, c0+1)
                // even lane holds (i,f); odd lane holds (g,o) of the same unit
                float s0 = evenp ? v2 : v0;
                float s1 = evenp ? v3 : v1;
                float r0x = __shfl_xor_sync(0xFFFFFFFFu, s0, 1);
                float r1x = __shfl_xor_sync(0xFFFFFFFFu, s1, 1);
                int ucol = n0w + ni*8 + 4*(tid4 >> 1);        // gate-i column of unit
                float iv, fv, gv, ov; int row;
                if (evenp) { iv = v0;  fv = v1;  gv = r0x; ov = r1x; row = m0w + gid; }
                else       { iv = r0x; fv = r1x; gv = v2;  ov = v3;  row = m0w + gid + 8; }
                float gi = sigf(  iv + sB[ucol+0]);
                float gf = sigf(  fv + sB[ucol+1]);
                float gg = tanhf( gv + sB[ucol+2]);
                float go = sigf(  ov + sB[ucol+3]);
                int u = Ubase + (ucol >> 2);
                size_t ci = (size_t)l*BH + (size_t)(bm0 + row)*Hd + u;
                float cnew = gf * g_c[ci] + gi * gg;
                float hnew = go * tanhf(cnew);
                g_c[ci] = cnew;
                g_h[ci] = hnew;
                __half hh = __float2half_rn(hnew);
                size_t bi = (size_t)(l*2 + p)*BH + (size_t)(bm0 + row)*Hd + u;
                g_bhi[bi] = hh;
                g_blo[bi] = __float2half_rn((hnew - __half2float(hh)) * LOSCALE);
            }
        }

        // y_{t-1}: warp-parallel, CTAs 96..127 (one row per warp)
        if (l == 0 && t >= 1 && bx >= 96)
            decode_row(Wfc, bfc, out, (bx - 96)*8 + warp, t - 1, lane);

        __threadfence();
        __syncthreads();
        if (tid == 0) atomicAdd(&g_barcnt, 1u);
    }

    // ---- tail: wait all phases, then y_63 + hT/cT in-kernel ----
    if (tid == 0) { while (*bc < 128u*128u) __nanosleep(40); }
    __syncthreads();

    if (bx < 32) decode_row(Wfc, bfc, out, bx*8 + warp, Td - 1, lane);

    {   // hT/cT copy: 128 CTAs x 256 threads, float4
        const float4* h4 = (const float4*)g_h;
        const float4* c4 = (const float4*)g_c;
        float4* o4 = (float4*)(out + (size_t)Bsz*Td*Od);
        const int n4 = Ld*BH/4;
        #pragma unroll 1
        for (int i = bx*256 + tid; i < n4; i += 128*256) {
            o4[i]      = h4[i];
            o4[n4 + i] = c4[i];
        }
    }
}

extern "C" void kernel_launch(void* const* d_in, const int* in_sizes, int n_in,
                              void* d_out, int out_size) {
    const float* x   = (const float*)d_in[0];
    const float* h0  = (const float*)d_in[1];
    const float* c0  = (const float*)d_in[2];
    const float* Wih = (const float*)d_in[3];
    const float* Whh = (const float*)d_in[4];
    const float* bih = (const float*)d_in[5];
    const float* bhh = (const float*)d_in[6];
    const float* Wfc = (const float*)d_in[7];
    const float* bfc = (const float*)d_in[8];
    float* out = (float*)d_out;

    static int smem_set = 0;
    if (!smem_set) {
        cudaFuncSetAttribute(lstm_persist, cudaFuncAttributeMaxDynamicSharedMemorySize, DSMEM);
        smem_set = 1;
    }

    prep_weights<<<(Ld*G4*Kd + 255)/256, 256>>>(Wih, Whh, bih, bhh);
    prep_state<<<(Ld*BH + 255)/256, 256>>>(x, h0, c0);
    lstm_persist<<<128, 256, DSMEM>>>(Wfc, bfc, out);
}

// round 17
// speedup vs baseline: 1.2626x; 1.2626x over previous
#include <cuda_runtime.h>
#include <cuda_fp16.h>
#include <math.h>
#include <stdint.h>

#define Bsz 256
#define Hd  512
#define Ld  2
#define Td  64
#define Od  7
#define G4  2048
#define Kd  1024
#define BH  (Bsz*Hd)

// ---- device scratch ----
__device__ __align__(16) __half g_Whi[Ld*G4*Kd];
__device__ float  g_bias[Ld*G4];
__device__ __align__(16) float  g_h[Ld*BH];
__device__ __align__(16) float  g_c[Ld*BH];
__device__ __align__(16) __half g_bhi[Ld*2*BH];   // [layer][parity][B][H]
__device__ __align__(16) __half g_xhi[BH];
__device__ unsigned g_barcnt;

__device__ __forceinline__ unsigned smaddr(const void* p) {
    return (unsigned)__cvta_generic_to_shared(p);
}
__device__ __forceinline__ void cp16(unsigned s, const void* g) {
    asm volatile("cp.async.cg.shared.global [%0], [%1], 16;\n" :: "r"(s), "l"(g));
}
__device__ __forceinline__ void ldsm4(unsigned* r, unsigned addr) {
    asm volatile("ldmatrix.sync.aligned.m8n8.x4.shared.b16 {%0,%1,%2,%3}, [%4];\n"
        : "=r"(r[0]), "=r"(r[1]), "=r"(r[2]), "=r"(r[3]) : "r"(addr));
}
__device__ __forceinline__ void mma16816(float* c, const unsigned* a, const unsigned* b) {
    asm volatile("mma.sync.aligned.m16n8k16.row.col.f32.f16.f16.f32 "
        "{%0,%1,%2,%3}, {%4,%5,%6,%7}, {%8,%9}, {%0,%1,%2,%3};\n"
        : "+f"(c[0]), "+f"(c[1]), "+f"(c[2]), "+f"(c[3])
        : "r"(a[0]), "r"(a[1]), "r"(a[2]), "r"(a[3]), "r"(b[0]), "r"(b[1]));
}
__device__ __forceinline__ float sigf(float x) { return 1.0f / (1.0f + expf(-x)); }

// warp-parallel decode: one row per warp, 7 outputs, shfl reduction
__device__ __forceinline__ void decode_row(const float* __restrict__ Wfc,
                                           const float* __restrict__ bfc,
                                           float* __restrict__ out,
                                           int R, int t, int lane) {
    const float4* h4 = (const float4*)(g_h + BH + (size_t)R*Hd);
    float4 hr[4];
    #pragma unroll
    for (int j = 0; j < 4; j++) hr[j] = h4[lane*4 + j];
    #pragma unroll
    for (int o = 0; o < Od; o++) {
        const float4* w4 = (const float4*)(Wfc + (size_t)o*Hd);
        float acc = 0.f;
        #pragma unroll
        for (int j = 0; j < 4; j++) {
            float4 w = w4[lane*4 + j];
            acc += hr[j].x*w.x + hr[j].y*w.y + hr[j].z*w.z + hr[j].w*w.w;
        }
        #pragma unroll
        for (int s = 16; s > 0; s >>= 1) acc += __shfl_down_sync(0xFFFFFFFFu, acc, s);
        if (lane == 0) out[(size_t)R*(Td*Od) + t*Od + o] = acc + bfc[o];
    }
}

// ---- prep ----
__global__ void prep_weights(const float* __restrict__ Wih, const float* __restrict__ Whh,
                             const float* __restrict__ bih, const float* __restrict__ bhh) {
    int idx = blockIdx.x * 256 + threadIdx.x;
    if (idx >= Ld*G4*Kd) return;
    int k = idx & (Kd - 1);
    int n = (idx >> 10) & (G4 - 1);
    int l = idx >> 21;
    int u = n >> 2, gi = n & 3;
    int srow = gi * Hd + u;
    float w = (k < Hd) ? Wih[((size_t)l*G4 + srow)*Hd + k]
                       : Whh[((size_t)l*G4 + srow)*Hd + (k - Hd)];
    g_Whi[idx] = __float2half_rn(w);
    if (k == 0) g_bias[l*G4 + n] = bih[l*G4 + srow] + bhh[l*G4 + srow];
}

__global__ void prep_state(const float* __restrict__ x, const float* __restrict__ h0,
                           const float* __restrict__ c0) {
    int idx = blockIdx.x * 256 + threadIdx.x;
    if (idx == 0) g_barcnt = 0u;
    if (idx >= Ld*BH) return;
    float h = h0[idx];
    g_h[idx] = h;
    g_c[idx] = c0[idx];
    int l = idx / BH, ru = idx - l*BH;
    g_bhi[(l*2 + 1)*BH + ru] = __float2half_rn(h);   // parity 1 = "previous" for t=0
    if (idx < BH) g_xhi[idx] = __float2half_rn(x[idx]);
}

// ---- persistent fused LSTM: split-phase, single-product fp16 GEMM ----
#define STRD  72                 // halves per smem row
#define ARRH  (64*STRD)          // halves per operand array
#define STGH  (2*ARRH)           // halves per stage [A, W] = 9216
#define STGB  (STGH*2)           // 18432 bytes
#define NSTG  8
#define DSMEM (NSTG*STGB)        // 147456 bytes

__global__ __launch_bounds__(256, 1)
void lstm_persist(const float* __restrict__ Wfc, const float* __restrict__ bfc,
                  float* __restrict__ out)
{
    const int bx = blockIdx.x;
    const int tid = threadIdx.x;

    const int mTile = bx & 3, nTile = bx >> 2;
    const int bm0 = mTile * 64, bn0 = nTile * 64;
    const int Ubase = bn0 >> 2;

    extern __shared__ __align__(16) __half dynsm[];
    __shared__ float sBias2[Ld][64];
    if (tid < 128) sBias2[tid >> 6][tid & 63] = g_bias[(tid >> 6)*G4 + bn0 + (tid & 63)];

    const __half* wH[2] = { g_Whi + (size_t)bn0 * Kd, g_Whi + ((size_t)G4 + bn0) * Kd };

    const int lane = tid & 31, warp = tid >> 5;
    const int wm = warp & 3, wn = warp >> 2;       // 4 x 2 warps, 16x32 each
    const int m0w = wm*16, n0w = wn*32;
    const int gid = lane >> 2, tid4 = lane & 3;

    const unsigned smB = smaddr(dynsm);
    const unsigned aBase = smB + 2u*((unsigned)(m0w + (lane & 15))*STRD + ((lane >> 4) << 3));
    const int g2 = lane >> 3;
    const unsigned bBase = smB + 2u*((unsigned)ARRH +
                           (unsigned)(n0w + (g2 >> 1)*8 + (lane & 7))*STRD + (unsigned)((g2 & 1) << 3));

    const __half *inpHi, *ownHi, *wHiBase;
    auto setPtrs = [&](int ph) {
        int t = ph >> 1, l = ph & 1;
        int p = t & 1, pp = p ^ 1;
        wHiBase = wH[l];
        if (l == 0) {
            inpHi = (t == 0) ? g_xhi : (g_bhi + (2 + pp)*BH);
            ownHi = g_bhi + pp*BH;
        } else {
            inpHi = g_bhi + p*BH;
            ownHi = g_bhi + (2 + pp)*BH;
        }
    };

    // chunk order: c<8 -> own half (k = 512 + 64c), c>=8 -> inp half (k = 64(c-8))
    auto load_chunk = [&](int c) {
        const __half* ah; int kcol, kw;
        if (c < 8) { ah = ownHi; kcol = 64*c;       kw = 512 + 64*c; }
        else       { ah = inpHi; kcol = 64*(c - 8); kw = 64*(c - 8); }
        __half* st = dynsm + (c & 7) * STGH;
        #pragma unroll
        for (int j = 0; j < 4; j++) {
            int q = tid + 256*j;             // 1024 quads: [A(512), W(512)]
            int arr = q >> 9, qq = q & 511;
            int row = qq >> 3, qc = qq & 7;
            unsigned so = (unsigned)(arr*ARRH + row*STRD + qc*8);
            const __half* src = arr ? (wHiBase + (size_t)row*Kd + kw + qc*8)
                                    : (ah + (size_t)(bm0 + row)*Hd + kcol + qc*8);
            cp16(smaddr(st + so), src);
        }
        asm volatile("cp.async.commit_group;\n");
    };

    auto gemm_chunk = [&](unsigned so, float (*acc)[4]) {
        #pragma unroll
        for (int kk = 0; kk < 64; kk += 16) {
            unsigned aH[4], bH[2][4];
            ldsm4(aH, aBase + so + 2u*(unsigned)kk);
            unsigned bd = bBase + so + 2u*(unsigned)kk;
            ldsm4(bH[0], bd);
            ldsm4(bH[1], bd + 2u*(unsigned)(16*STRD));
            #pragma unroll
            for (int ni = 0; ni < 4; ni++)
                mma16816(acc[ni], aH, &bH[ni >> 1][(ni & 1)*2]);
        }
    };

    // prologue: own-half of phase 0
    setPtrs(0);
    #pragma unroll 1
    for (int c = 0; c < 8; c++) load_chunk(c);

    volatile unsigned* bc = &g_barcnt;

    for (int ph = 0; ph < 128; ph++) {
        const int t = ph >> 1, l = ph & 1;
        const int p = t & 1;

        float acc[4][4] = {};

        // ---- own half: all 8 chunks resident, no per-chunk barriers ----
        asm volatile("cp.async.wait_group 0;\n");
        __syncthreads();
        #pragma unroll 2
        for (int c = 0; c < 8; c++)
            gemm_chunk((unsigned)(c * STGB), acc);

        // ---- global barrier: all CTAs finished phase ph-1 ----
        if (tid == 0) {
            unsigned tgt = 128u * (unsigned)ph;
            while (*bc < tgt) __nanosleep(40);
        }
        __syncthreads();     // orders own-stage reads before inp overwrites

        // ---- inp half: load + compute 8 chunks ----
        #pragma unroll 1
        for (int c = 8; c < 16; c++) load_chunk(c);

        #pragma unroll 1
        for (int c = 8; c < 16; c++) {
            switch (15 - c) {
                case 7: asm volatile("cp.async.wait_group 7;\n"); break;
                case 6: asm volatile("cp.async.wait_group 6;\n"); break;
                case 5: asm volatile("cp.async.wait_group 5;\n"); break;
                case 4: asm volatile("cp.async.wait_group 4;\n"); break;
                case 3: asm volatile("cp.async.wait_group 3;\n"); break;
                case 2: asm volatile("cp.async.wait_group 2;\n"); break;
                case 1: asm volatile("cp.async.wait_group 1;\n"); break;
                default: asm volatile("cp.async.wait_group 0;\n"); break;
            }
            __syncthreads();
            gemm_chunk((unsigned)((c & 7) * STGB), acc);
        }

        // ---- epilogue: gate tile in smem (stage-0 region; safe per sync pattern) ----
        float* sG = reinterpret_cast<float*>(dynsm);
        #pragma unroll
        for (int ni = 0; ni < 4; ni++) {
            int r0 = m0w + gid;
            int c0 = n0w + ni*8 + 2*tid4;
            sG[r0*66 + c0]       = acc[ni][0];
            sG[r0*66 + c0 + 1]   = acc[ni][1];
            sG[(r0+8)*66 + c0]   = acc[ni][2];
            sG[(r0+8)*66 + c0+1] = acc[ni][3];
        }
        __syncthreads();

        {
            const float* sB = sBias2[l];
            #pragma unroll
            for (int s = 0; s < 4; s++) {
                int pi = tid + 256*s;
                int r = pi >> 4, u = pi & 15;
                float gi = sigf(  sG[r*66 + 4*u + 0] + sB[4*u + 0]);
                float gf = sigf(  sG[r*66 + 4*u + 1] + sB[4*u + 1]);
                float gg = tanhf( sG[r*66 + 4*u + 2] + sB[4*u + 2]);
                float go = sigf(  sG[r*66 + 4*u + 3] + sB[4*u + 3]);
                size_t ci = (size_t)l*BH + (size_t)(bm0 + r)*Hd + Ubase + u;
                float cnew = gf * g_c[ci] + gi * gg;
                float hnew = go * tanhf(cnew);
                g_c[ci] = cnew;
                g_h[ci] = hnew;
                size_t bi = (size_t)(l*2 + p)*BH + (size_t)(bm0 + r)*Hd + Ubase + u;
                g_bhi[bi] = __float2half_rn(hnew);
            }
        }

        // y_{t-1}: warp-parallel, CTAs 96..127 (one row per warp)
        if (l == 0 && t >= 1 && bx >= 96)
            decode_row(Wfc, bfc, out, (bx - 96)*8 + warp, t - 1, lane);

        __threadfence();
        __syncthreads();
        if (tid == 0) atomicAdd(&g_barcnt, 1u);

        if (ph + 1 < 128) {           // prefetch next phase's own half (data from ph-1: done)
            setPtrs(ph + 1);
            #pragma unroll 1
            for (int c = 0; c < 8; c++) load_chunk(c);
        }
    }

    // ---- tail: wait all phases, then y_63 + hT/cT in-kernel ----
    if (tid == 0) { while (*bc < 128u*128u) __nanosleep(40); }
    __syncthreads();

    if (bx < 32) decode_row(Wfc, bfc, out, bx*8 + warp, Td - 1, lane);

    {   // hT/cT copy: 128 CTAs x 256 threads, float4
        const float4* h4 = (const float4*)g_h;
        const float4* c4 = (const float4*)g_c;
        float4* o4 = (float4*)(out + (size_t)Bsz*Td*Od);
        const int n4 = Ld*BH/4;
        #pragma unroll 1
        for (int i = bx*256 + tid; i < n4; i += 128*256) {
            o4[i]      = h4[i];
            o4[n4 + i] = c4[i];
        }
    }
}

extern "C" void kernel_launch(void* const* d_in, const int* in_sizes, int n_in,
                              void* d_out, int out_size) {
    const float* x   = (const float*)d_in[0];
    const float* h0  = (const float*)d_in[1];
    const float* c0  = (const float*)d_in[2];
    const float* Wih = (const float*)d_in[3];
    const float* Whh = (const float*)d_in[4];
    const float* bih = (const float*)d_in[5];
    const float* bhh = (const float*)d_in[6];
    const float* Wfc = (const float*)d_in[7];
    const float* bfc = (const float*)d_in[8];
    float* out = (float*)d_out;

    static int smem_set = 0;
    if (!smem_set) {
        cudaFuncSetAttribute(lstm_persist, cudaFuncAttributeMaxDynamicSharedMemorySize, DSMEM);
        smem_set = 1;
    }

    prep_weights<<<(Ld*G4*Kd + 255)/256, 256>>>(Wih, Whh, bih, bhh);
    prep_state<<<(Ld*BH + 255)/256, 256>>>(x, h0, c0);
    lstm_persist<<<128, 256, DSMEM>>>(Wfc, bfc, out);
}